// round 1
// baseline (speedup 1.0000x reference)
#include <cuda_runtime.h>
#include <math.h>

#define N_NODES 10000
#define N_EDGES 320000

// output region offsets in floats (outputs concatenated in reference return order)
#define OFF_NODE_EMB   0L
#define OFF_EDGE_EMB   80000L
#define OFF_RECON_NODE 2640000L
#define OFF_RECON_EDGE 3280000L
#define OFF_ADJ        13520000L
#define OFF_COORD      113520000L

// scratch (global, persistent across graph replays -> re-initialized every launch)
__device__ float g_A[N_NODES * 128];          // nf @ W1[0:64]  + b1
__device__ float g_B[N_NODES * 128];          // nf @ W1[64:128]
__device__ float g_h[(long)N_EDGES * 128];    // relu(edge layer-1)
__device__ float g_hn[N_NODES * 128];         // relu(node layer-1)
__device__ float g_agg[N_NODES * 32];         // segment_sum(edge_out)
__device__ float g_emb[N_NODES * 8];          // node_emb copy for adj kernel
__device__ float g_r[N_NODES];                // ||node_emb||^2

// ---------------------------------------------------------------------------
// K0: zero agg accumulator; init coord_out region of d_out with coords
// ---------------------------------------------------------------------------
__global__ void k_init(const float* __restrict__ coords, float* __restrict__ out) {
    int i = blockIdx.x * blockDim.x + threadIdx.x;
    if (i < N_NODES * 32) g_agg[i] = 0.f;
    if (i < N_NODES * 3)  out[OFF_COORD + i] = coords[i];
}

// ---------------------------------------------------------------------------
// K1: per-node projections A = nf @ W1rows + (b1), one of A/B selected by `which`
// block = 128 threads (one hidden unit each), weights staged in smem
// ---------------------------------------------------------------------------
__global__ __launch_bounds__(128) void k_nodeproj(int which,
                                                  const float* __restrict__ nf,
                                                  const float* __restrict__ w,   // [64,128]
                                                  const float* __restrict__ b) { // [128] or null
    __shared__ float ws[64 * 128];
    __shared__ float xs[64];
    float* dst = which ? g_B : g_A;
    int tid = threadIdx.x;
    for (int i = tid; i < 64 * 128; i += 128) ws[i] = w[i];
    float bias = b ? b[tid] : 0.f;
    __syncthreads();
    for (int n = blockIdx.x; n < N_NODES; n += gridDim.x) {
        if (tid < 64) xs[tid] = nf[n * 64 + tid];
        __syncthreads();
        float acc = bias;
#pragma unroll
        for (int f = 0; f < 64; f++) acc = fmaf(xs[f], ws[f * 128 + tid], acc);
        dst[n * 128 + tid] = acc;
        __syncthreads();
    }
}

// ---------------------------------------------------------------------------
// K2: edge layer-1.  h[e][k] = relu(A[row][k] + B[col][k] + radial*w1r[k] + ea@W1e[:,k])
// 256 threads = 2 edge slots x 128 k.  W1e column (32 floats) in registers.
// ---------------------------------------------------------------------------
__global__ __launch_bounds__(256) void k_edge_h(const float* __restrict__ ew1,  // [161,128]
                                                const int* __restrict__ ei,
                                                const float* __restrict__ ea,
                                                const float* __restrict__ coords) {
    int tid = threadIdx.x;
    int k = tid & 127, slot = tid >> 7, lane = tid & 31;
    float w1e[32];
#pragma unroll
    for (int t = 0; t < 32; t++) w1e[t] = ew1[(128 + t) * 128 + k];
    float w1r = ew1[160 * 128 + k];
    for (int e0 = blockIdx.x * 2; e0 < N_EDGES; e0 += gridDim.x * 2) {
        int e = e0 + slot;
        int row = ei[e], col = ei[N_EDGES + e];
        float d0 = coords[row * 3 + 0] - coords[col * 3 + 0];
        float d1 = coords[row * 3 + 1] - coords[col * 3 + 1];
        float d2 = coords[row * 3 + 2] - coords[col * 3 + 2];
        float radial = d0 * d0 + d1 * d1 + d2 * d2;
        float eav = ea[e * 32 + lane];
        float h = g_A[row * 128 + k] + g_B[col * 128 + k] + radial * w1r;
#pragma unroll
        for (int t = 0; t < 32; t++)
            h = fmaf(__shfl_sync(0xffffffffu, eav, t), w1e[t], h);
        g_h[(long)e * 128 + k] = fmaxf(h, 0.f);
    }
}

// ---------------------------------------------------------------------------
// K3: edge layer-2 + full fused epilogue.
// 256 threads = 2 edge groups x (4 k-quarters x 32 j).  W2 sub-column in regs.
// Group reduces partials in smem; warp kq==0 then computes:
//   edge_out -> agg atomics, edge_emb, recon_edge, coord weight -> coord atomics
// ---------------------------------------------------------------------------
__global__ __launch_bounds__(256) void k_edge_out(
        const float* __restrict__ ew2, const float* __restrict__ eb2,
        const float* __restrict__ cw1, const float* __restrict__ cb1,
        const float* __restrict__ cw2,
        const float* __restrict__ few, const float* __restrict__ feb,
        const float* __restrict__ dew, const float* __restrict__ deb,
        const int* __restrict__ ei, const float* __restrict__ coords,
        float* __restrict__ out) {
    __shared__ float part[2][4][32];
    __shared__ float s_b2[32], s_fcw[256], s_fcb[8], s_cw1[64], s_dew[256], s_deb[32], s_misc[4];
    int tid = threadIdx.x;
    if (tid < 32) { s_b2[tid] = eb2[tid]; s_deb[tid] = deb[tid]; }
    s_fcw[tid] = few[tid];        // 32*8 = 256
    s_dew[tid] = dew[tid];        // 8*32 = 256
    if (tid < 64) s_cw1[tid] = cw1[tid];
    if (tid < 8)  s_fcb[tid] = feb[tid];
    if (tid == 0) { s_misc[0] = cb1[0]; s_misc[1] = cb1[1]; s_misc[2] = cw2[0]; s_misc[3] = cw2[1]; }
    int g = tid >> 7, kq = (tid >> 5) & 3, j = tid & 31;
    float w2r[32];
#pragma unroll
    for (int t = 0; t < 32; t++) w2r[t] = ew2[(kq * 32 + t) * 32 + j];
    __syncthreads();
    for (int e0 = blockIdx.x * 2; e0 < N_EDGES; e0 += gridDim.x * 2) {
        int e = e0 + g;
        float hv = g_h[(long)e * 128 + kq * 32 + j];
        float partial = 0.f;
#pragma unroll
        for (int t = 0; t < 32; t++)
            partial = fmaf(__shfl_sync(0xffffffffu, hv, t), w2r[t], partial);
        part[g][kq][j] = partial;
        __syncthreads();
        if (kq == 0) {
            float ov = part[g][0][j] + part[g][1][j] + part[g][2][j] + part[g][3][j] + s_b2[j];
            int row = ei[e];
            atomicAdd(&g_agg[row * 32 + j], ov);
            float p[10];
#pragma unroll
            for (int r = 0; r < 8; r++) p[r] = ov * s_fcw[j * 8 + r];
            p[8] = ov * s_cw1[j * 2 + 0];
            p[9] = ov * s_cw1[j * 2 + 1];
#pragma unroll
            for (int off = 16; off > 0; off >>= 1) {
#pragma unroll
                for (int r = 0; r < 10; r++) p[r] += __shfl_xor_sync(0xffffffffu, p[r], off);
            }
            float er[8];
#pragma unroll
            for (int r = 0; r < 8; r++) er[r] = p[r] + s_fcb[r];
            if (j == 0) {
                float4* o = (float4*)(out + OFF_EDGE_EMB + (long)e * 8);
                o[0] = make_float4(er[0], er[1], er[2], er[3]);
                o[1] = make_float4(er[4], er[5], er[6], er[7]);
            }
            float rec = s_deb[j];
#pragma unroll
            for (int r = 0; r < 8; r++) rec = fmaf(er[r], s_dew[r * 32 + j], rec);
            out[OFF_RECON_EDGE + (long)e * 32 + j] = rec;
            float wz = fmaxf(p[8] + s_misc[0], 0.f) * s_misc[2] +
                       fmaxf(p[9] + s_misc[1], 0.f) * s_misc[3];
            if (j < 3) {
                int col = ei[N_EDGES + e];
                float dd0 = coords[row * 3 + 0] - coords[col * 3 + 0];
                float dd1 = coords[row * 3 + 1] - coords[col * 3 + 1];
                float dd2 = coords[row * 3 + 2] - coords[col * 3 + 2];
                float rad = dd0 * dd0 + dd1 * dd1 + dd2 * dd2;
                float inv = 1.0f / (sqrtf(rad) + 1.0f);
                float dj = (j == 0) ? dd0 : (j == 1) ? dd1 : dd2;
                atomicAdd(out + OFF_COORD + row * 3 + j, dj * inv * wz);
            }
        }
        __syncthreads();
    }
}

// ---------------------------------------------------------------------------
// K4a: node layer-1.  node_in = [nf(64), agg(32), coord_out(3)] @ nw1 + b1, relu
// 256 threads = 2 node slots x 128 k.  nw1 columns read via __ldg (L1-resident).
// ---------------------------------------------------------------------------
__global__ __launch_bounds__(256) void k_node_h(const float* __restrict__ nw1,  // [99,128]
                                                const float* __restrict__ nb1,
                                                const float* __restrict__ nf,
                                                const float* __restrict__ outc) {
    int tid = threadIdx.x;
    int k = tid & 127, slot = tid >> 7, lane = tid & 31;
    float bias = nb1[k];
    float wc0 = nw1[96 * 128 + k], wc1 = nw1[97 * 128 + k], wc2 = nw1[98 * 128 + k];
    for (int n0 = blockIdx.x * 2; n0 < N_NODES; n0 += gridDim.x * 2) {
        int n = n0 + slot;
        float xa = nf[n * 64 + lane];
        float xb = nf[n * 64 + 32 + lane];
        float xc = g_agg[n * 32 + lane];
        float h = bias;
#pragma unroll
        for (int t = 0; t < 32; t++)
            h = fmaf(__shfl_sync(0xffffffffu, xa, t), __ldg(nw1 + t * 128 + k), h);
#pragma unroll
        for (int t = 0; t < 32; t++)
            h = fmaf(__shfl_sync(0xffffffffu, xb, t), __ldg(nw1 + (32 + t) * 128 + k), h);
#pragma unroll
        for (int t = 0; t < 32; t++)
            h = fmaf(__shfl_sync(0xffffffffu, xc, t), __ldg(nw1 + (64 + t) * 128 + k), h);
        h = fmaf(outc[n * 3 + 0], wc0, h);
        h = fmaf(outc[n * 3 + 1], wc1, h);
        h = fmaf(outc[n * 3 + 2], wc2, h);
        g_hn[n * 128 + k] = fmaxf(h, 0.f);
    }
}

// ---------------------------------------------------------------------------
// K4b: node layer-2 + node_emb / r / recon_node epilogue.
// 256 threads = 4 node slots x 64 j (2 warps per slot).
// ---------------------------------------------------------------------------
__global__ __launch_bounds__(256) void k_node_out(
        const float* __restrict__ nw2, const float* __restrict__ nb2,
        const float* __restrict__ fnw, const float* __restrict__ fnb,
        const float* __restrict__ dnw, const float* __restrict__ dnb,
        float* __restrict__ out) {
    __shared__ float ps[4][2][8];
    int tid = threadIdx.x;
    int slot = tid >> 6, jj = tid & 63, half = (tid >> 5) & 1, lane = tid & 31;
    float bias = nb2[jj];
    for (int n0 = blockIdx.x * 4; n0 < N_NODES; n0 += gridDim.x * 4) {
        int n = n0 + slot;
        const float* hrow = g_hn + n * 128;
        float acc = bias;
#pragma unroll 8
        for (int kk = 0; kk < 128; kk++)
            acc = fmaf(__ldg(hrow + kk), __ldg(nw2 + kk * 64 + jj), acc);
        float p[8];
#pragma unroll
        for (int r = 0; r < 8; r++) p[r] = acc * __ldg(fnw + jj * 8 + r);
#pragma unroll
        for (int off = 16; off > 0; off >>= 1) {
#pragma unroll
            for (int r = 0; r < 8; r++) p[r] += __shfl_xor_sync(0xffffffffu, p[r], off);
        }
        if (lane == 0) {
#pragma unroll
            for (int r = 0; r < 8; r++) ps[slot][half][r] = p[r];
        }
        __syncthreads();
        float er[8];
#pragma unroll
        for (int r = 0; r < 8; r++) er[r] = ps[slot][0][r] + ps[slot][1][r] + __ldg(fnb + r);
        if (jj == 0) {
            float4 v0 = make_float4(er[0], er[1], er[2], er[3]);
            float4 v1 = make_float4(er[4], er[5], er[6], er[7]);
            ((float4*)(out + OFF_NODE_EMB + (long)n * 8))[0] = v0;
            ((float4*)(out + OFF_NODE_EMB + (long)n * 8))[1] = v1;
            ((float4*)(g_emb + n * 8))[0] = v0;
            ((float4*)(g_emb + n * 8))[1] = v1;
            float rr = 0.f;
#pragma unroll
            for (int r = 0; r < 8; r++) rr = fmaf(er[r], er[r], rr);
            g_r[n] = rr;
        }
        float rec = __ldg(dnb + jj);
#pragma unroll
        for (int r = 0; r < 8; r++) rec = fmaf(er[r], __ldg(dnw + r * 64 + jj), rec);
        out[OFF_RECON_NODE + (long)n * 64 + jj] = rec;
        __syncthreads();
    }
}

// ---------------------------------------------------------------------------
// K5: adjacency.  adj[i][j] = sigmoid(3*(r_i + r_j - 2<e_i,e_j>) - 1), diag 0.
// block = 256 threads, tile = 16 rows x 1024 cols; column embs in registers.
// ---------------------------------------------------------------------------
__global__ __launch_bounds__(256) void k_adj(float* __restrict__ out) {
    int tid = threadIdx.x;
    int j0 = blockIdx.x * 1024 + tid * 4;
    float ej[4][8], rj[4];
#pragma unroll
    for (int q = 0; q < 4; q++) {
        int jx = j0 + q;
        if (jx < N_NODES) {
            float4 a = ((const float4*)(g_emb + jx * 8))[0];
            float4 b = ((const float4*)(g_emb + jx * 8))[1];
            ej[q][0] = a.x; ej[q][1] = a.y; ej[q][2] = a.z; ej[q][3] = a.w;
            ej[q][4] = b.x; ej[q][5] = b.y; ej[q][6] = b.z; ej[q][7] = b.w;
            rj[q] = g_r[jx];
        } else {
#pragma unroll
            for (int r = 0; r < 8; r++) ej[q][r] = 0.f;
            rj[q] = 0.f;
        }
    }
    int ibase = blockIdx.y * 16;   // 625 * 16 == 10000 exactly
    for (int ii = 0; ii < 16; ii++) {
        int i = ibase + ii;
        float4 a = ((const float4*)(g_emb + i * 8))[0];
        float4 b = ((const float4*)(g_emb + i * 8))[1];
        float eiv[8] = {a.x, a.y, a.z, a.w, b.x, b.y, b.z, b.w};
        float ri = g_r[i];
        float res[4];
#pragma unroll
        for (int q = 0; q < 4; q++) {
            float dot = 0.f;
#pragma unroll
            for (int r = 0; r < 8; r++) dot = fmaf(eiv[r], ej[q][r], dot);
            float d2 = ri + rj[q] - 2.f * dot;
            float ex = __expf(1.f - 3.f * d2);
            float v = __fdividef(1.f, 1.f + ex);
            res[q] = (j0 + q == i) ? 0.f : v;
        }
        if (j0 < N_NODES) {
            *((float4*)(out + OFF_ADJ + (long)i * N_NODES + j0)) =
                make_float4(res[0], res[1], res[2], res[3]);
        }
    }
}

// ---------------------------------------------------------------------------
extern "C" void kernel_launch(void* const* d_in, const int* in_sizes, int n_in,
                              void* d_out, int out_size) {
    const float* nf     = (const float*)d_in[0];
    const int*   ei     = (const int*)  d_in[1];
    const float* ea     = (const float*)d_in[2];
    const float* coords = (const float*)d_in[3];
    const float* ew1    = (const float*)d_in[4];
    const float* eb1    = (const float*)d_in[5];
    const float* ew2    = (const float*)d_in[6];
    const float* eb2    = (const float*)d_in[7];
    const float* cw1    = (const float*)d_in[8];
    const float* cb1    = (const float*)d_in[9];
    const float* cw2    = (const float*)d_in[10];
    const float* nw1    = (const float*)d_in[11];
    const float* nb1    = (const float*)d_in[12];
    const float* nw2    = (const float*)d_in[13];
    const float* nb2    = (const float*)d_in[14];
    const float* fnw    = (const float*)d_in[15];
    const float* fnb    = (const float*)d_in[16];
    const float* few    = (const float*)d_in[17];
    const float* feb    = (const float*)d_in[18];
    const float* dnw    = (const float*)d_in[19];
    const float* dnb    = (const float*)d_in[20];
    const float* dew    = (const float*)d_in[21];
    const float* deb    = (const float*)d_in[22];
    float* out = (float*)d_out;

    k_init<<<(N_NODES * 32 + 255) / 256, 256>>>(coords, out);
    k_nodeproj<<<592, 128>>>(0, nf, ew1, eb1);             // A = nf@W1[0:64] + b1
    k_nodeproj<<<592, 128>>>(1, nf, ew1 + 64 * 128, 0);    // B = nf@W1[64:128]
    k_edge_h<<<592, 256>>>(ew1, ei, ea, coords);
    k_edge_out<<<592, 256>>>(ew2, eb2, cw1, cb1, cw2, few, feb, dew, deb, ei, coords, out);
    k_node_h<<<592, 256>>>(nw1, nb1, nf, out + OFF_COORD);
    k_node_out<<<592, 256>>>(nw2, nb2, fnw, fnb, dnw, dnb, out);
    dim3 gadj((N_NODES + 1023) / 1024, N_NODES / 16);
    k_adj<<<gadj, 256>>>(out);
}

// round 2
// speedup vs baseline: 1.3430x; 1.3430x over previous
#include <cuda_runtime.h>
#include <math.h>

#define N_NODES 10000
#define N_EDGES 320000

// output region offsets in floats (outputs concatenated in reference return order)
#define OFF_NODE_EMB   0L
#define OFF_EDGE_EMB   80000L
#define OFF_RECON_NODE 2640000L
#define OFF_RECON_EDGE 3280000L
#define OFF_ADJ        13520000L
#define OFF_COORD      113520000L

// scratch (global, persistent across graph replays -> re-initialized every launch)
__device__ float g_A[N_NODES * 128];          // nf @ W1[0:64]  + b1
__device__ float g_B[N_NODES * 128];          // nf @ W1[64:128]
__device__ float g_hn[N_NODES * 128];         // relu(node layer-1)
__device__ float g_agg[N_NODES * 32];         // segment_sum(edge_out)
__device__ float g_emb[N_NODES * 8];          // node_emb copy for adj kernel
__device__ float g_r[N_NODES];                // ||node_emb||^2

// ---------------------------------------------------------------------------
// K0: zero agg accumulator; init coord_out region of d_out with coords
// ---------------------------------------------------------------------------
__global__ void k_init(const float* __restrict__ coords, float* __restrict__ out) {
    int i = blockIdx.x * blockDim.x + threadIdx.x;
    if (i < N_NODES * 32) g_agg[i] = 0.f;
    if (i < N_NODES * 3)  out[OFF_COORD + i] = coords[i];
}

// ---------------------------------------------------------------------------
// K1: per-node projections A = nf @ W1rows + (b1), one of A/B selected by `which`
// ---------------------------------------------------------------------------
__global__ __launch_bounds__(128) void k_nodeproj(int which,
                                                  const float* __restrict__ nf,
                                                  const float* __restrict__ w,   // [64,128]
                                                  const float* __restrict__ b) { // [128] or null
    __shared__ float ws[64 * 128];
    __shared__ float xs[64];
    float* dst = which ? g_B : g_A;
    int tid = threadIdx.x;
    for (int i = tid; i < 64 * 128; i += 128) ws[i] = w[i];
    float bias = b ? b[tid] : 0.f;
    __syncthreads();
    for (int n = blockIdx.x; n < N_NODES; n += gridDim.x) {
        if (tid < 64) xs[tid] = nf[n * 64 + tid];
        __syncthreads();
        float acc = bias;
#pragma unroll
        for (int f = 0; f < 64; f++) acc = fmaf(xs[f], ws[f * 128 + tid], acc);
        dst[n * 128 + tid] = acc;
        __syncthreads();
    }
}

// ---------------------------------------------------------------------------
// K2: FUSED edge layer-1 + layer-2 + epilogue.
// 256 threads = 2 edge groups x 128.  Per group, per edge:
//   h_k = relu(A[row][k] + B[col][k] + radial*w1r[k] + ea . W1e[:,k])
//       (ea staged in smem, read as float4 broadcasts; W1e column in regs)
//   h staged in smem -> each warp reduces its 32-k slice for all 32 j
//   kq==0 warp: edge_out -> agg atomics, edge_emb, recon_edge, coord atomics
// ---------------------------------------------------------------------------
__global__ __launch_bounds__(256, 2) void k_edge_fused(
        const float* __restrict__ ew1,  // [161,128]
        const float* __restrict__ ew2, const float* __restrict__ eb2,
        const float* __restrict__ cw1, const float* __restrict__ cb1,
        const float* __restrict__ cw2,
        const float* __restrict__ few, const float* __restrict__ feb,
        const float* __restrict__ dew, const float* __restrict__ deb,
        const int* __restrict__ ei, const float* __restrict__ ea,
        const float* __restrict__ coords,
        float* __restrict__ out) {
    __shared__ __align__(16) float eas[2][32];
    __shared__ __align__(16) float hs[2][128];
    __shared__ float part[2][4][32];
    __shared__ float s_b2[32], s_fcw[256], s_fcb[8], s_cw1[64], s_dew[256], s_deb[32], s_misc[4];
    int tid = threadIdx.x;
    int g = tid >> 7, k = tid & 127, kq = (tid >> 5) & 3, j = tid & 31;

    if (tid < 32) { s_b2[tid] = eb2[tid]; s_deb[tid] = deb[tid]; }
    s_fcw[tid] = few[tid];        // 32*8 = 256
    s_dew[tid] = dew[tid];        // 8*32 = 256
    if (tid < 64) s_cw1[tid] = cw1[tid];
    if (tid < 8)  s_fcb[tid] = feb[tid];
    if (tid == 0) { s_misc[0] = cb1[0]; s_misc[1] = cb1[1]; s_misc[2] = cw2[0]; s_misc[3] = cw2[1]; }

    float w1e[32];                 // W1e column k
#pragma unroll
    for (int t = 0; t < 32; t++) w1e[t] = ew1[(128 + t) * 128 + k];
    float w1r = ew1[160 * 128 + k];
    float w2r[32];                 // W2 sub-column: rows [kq*32, kq*32+32) of col j
#pragma unroll
    for (int t = 0; t < 32; t++) w2r[t] = ew2[(kq * 32 + t) * 32 + j];
    __syncthreads();

    for (int e0 = blockIdx.x * 2; e0 < N_EDGES; e0 += gridDim.x * 2) {
        int e = e0 + g;
        int row = ei[e], col = ei[N_EDGES + e];
        float d0 = coords[row * 3 + 0] - coords[col * 3 + 0];
        float d1 = coords[row * 3 + 1] - coords[col * 3 + 1];
        float d2 = coords[row * 3 + 2] - coords[col * 3 + 2];
        float radial = d0 * d0 + d1 * d1 + d2 * d2;
        if (kq == 3) eas[g][j] = ea[e * 32 + j];
        __syncthreads();

        // layer 1
        float h = g_A[row * 128 + k] + g_B[col * 128 + k] + radial * w1r;
        const float4* ev = (const float4*)eas[g];
#pragma unroll
        for (int q = 0; q < 8; q++) {
            float4 v = ev[q];
            h = fmaf(v.x, w1e[q * 4 + 0], h);
            h = fmaf(v.y, w1e[q * 4 + 1], h);
            h = fmaf(v.z, w1e[q * 4 + 2], h);
            h = fmaf(v.w, w1e[q * 4 + 3], h);
        }
        hs[g][k] = fmaxf(h, 0.f);
        __syncthreads();

        // layer 2: each warp reduces its 32-k slice for all 32 j
        const float4* hv = (const float4*)(hs[g] + kq * 32);
        float partial = 0.f;
#pragma unroll
        for (int q = 0; q < 8; q++) {
            float4 v = hv[q];
            partial = fmaf(v.x, w2r[q * 4 + 0], partial);
            partial = fmaf(v.y, w2r[q * 4 + 1], partial);
            partial = fmaf(v.z, w2r[q * 4 + 2], partial);
            partial = fmaf(v.w, w2r[q * 4 + 3], partial);
        }
        part[g][kq][j] = partial;
        __syncthreads();

        if (kq == 0) {
            float ov = part[g][0][j] + part[g][1][j] + part[g][2][j] + part[g][3][j] + s_b2[j];
            atomicAdd(&g_agg[row * 32 + j], ov);
            float p[10];
#pragma unroll
            for (int r = 0; r < 8; r++) p[r] = ov * s_fcw[j * 8 + r];
            p[8] = ov * s_cw1[j * 2 + 0];
            p[9] = ov * s_cw1[j * 2 + 1];
#pragma unroll
            for (int off = 16; off > 0; off >>= 1) {
#pragma unroll
                for (int r = 0; r < 10; r++) p[r] += __shfl_xor_sync(0xffffffffu, p[r], off);
            }
            float er[8];
#pragma unroll
            for (int r = 0; r < 8; r++) er[r] = p[r] + s_fcb[r];
            if (j == 0) {
                float4* o = (float4*)(out + OFF_EDGE_EMB + (long)e * 8);
                o[0] = make_float4(er[0], er[1], er[2], er[3]);
                o[1] = make_float4(er[4], er[5], er[6], er[7]);
            }
            float rec = s_deb[j];
#pragma unroll
            for (int r = 0; r < 8; r++) rec = fmaf(er[r], s_dew[r * 32 + j], rec);
            out[OFF_RECON_EDGE + (long)e * 32 + j] = rec;
            float wz = fmaxf(p[8] + s_misc[0], 0.f) * s_misc[2] +
                       fmaxf(p[9] + s_misc[1], 0.f) * s_misc[3];
            if (j < 3) {
                float inv = 1.0f / (sqrtf(radial) + 1.0f);
                float dj = (j == 0) ? d0 : (j == 1) ? d1 : d2;
                atomicAdd(out + OFF_COORD + row * 3 + j, dj * inv * wz);
            }
        }
    }
}

// ---------------------------------------------------------------------------
// K4a: node layer-1.  node_in = [nf(64), agg(32), coord_out(3)] @ nw1 + b1, relu
// ---------------------------------------------------------------------------
__global__ __launch_bounds__(256) void k_node_h(const float* __restrict__ nw1,  // [99,128]
                                                const float* __restrict__ nb1,
                                                const float* __restrict__ nf,
                                                const float* __restrict__ outc) {
    int tid = threadIdx.x;
    int k = tid & 127, slot = tid >> 7, lane = tid & 31;
    float bias = nb1[k];
    float wc0 = nw1[96 * 128 + k], wc1 = nw1[97 * 128 + k], wc2 = nw1[98 * 128 + k];
    for (int n0 = blockIdx.x * 2; n0 < N_NODES; n0 += gridDim.x * 2) {
        int n = n0 + slot;
        float xa = nf[n * 64 + lane];
        float xb = nf[n * 64 + 32 + lane];
        float xc = g_agg[n * 32 + lane];
        float h = bias;
#pragma unroll
        for (int t = 0; t < 32; t++)
            h = fmaf(__shfl_sync(0xffffffffu, xa, t), __ldg(nw1 + t * 128 + k), h);
#pragma unroll
        for (int t = 0; t < 32; t++)
            h = fmaf(__shfl_sync(0xffffffffu, xb, t), __ldg(nw1 + (32 + t) * 128 + k), h);
#pragma unroll
        for (int t = 0; t < 32; t++)
            h = fmaf(__shfl_sync(0xffffffffu, xc, t), __ldg(nw1 + (64 + t) * 128 + k), h);
        h = fmaf(outc[n * 3 + 0], wc0, h);
        h = fmaf(outc[n * 3 + 1], wc1, h);
        h = fmaf(outc[n * 3 + 2], wc2, h);
        g_hn[n * 128 + k] = fmaxf(h, 0.f);
    }
}

// ---------------------------------------------------------------------------
// K4b: node layer-2 + node_emb / r / recon_node epilogue.
// ---------------------------------------------------------------------------
__global__ __launch_bounds__(256) void k_node_out(
        const float* __restrict__ nw2, const float* __restrict__ nb2,
        const float* __restrict__ fnw, const float* __restrict__ fnb,
        const float* __restrict__ dnw, const float* __restrict__ dnb,
        float* __restrict__ out) {
    __shared__ float ps[4][2][8];
    int tid = threadIdx.x;
    int slot = tid >> 6, jj = tid & 63, half = (tid >> 5) & 1, lane = tid & 31;
    float bias = nb2[jj];
    for (int n0 = blockIdx.x * 4; n0 < N_NODES; n0 += gridDim.x * 4) {
        int n = n0 + slot;
        const float* hrow = g_hn + n * 128;
        float acc = bias;
#pragma unroll 8
        for (int kk = 0; kk < 128; kk++)
            acc = fmaf(__ldg(hrow + kk), __ldg(nw2 + kk * 64 + jj), acc);
        float p[8];
#pragma unroll
        for (int r = 0; r < 8; r++) p[r] = acc * __ldg(fnw + jj * 8 + r);
#pragma unroll
        for (int off = 16; off > 0; off >>= 1) {
#pragma unroll
            for (int r = 0; r < 8; r++) p[r] += __shfl_xor_sync(0xffffffffu, p[r], off);
        }
        if (lane == 0) {
#pragma unroll
            for (int r = 0; r < 8; r++) ps[slot][half][r] = p[r];
        }
        __syncthreads();
        float er[8];
#pragma unroll
        for (int r = 0; r < 8; r++) er[r] = ps[slot][0][r] + ps[slot][1][r] + __ldg(fnb + r);
        if (jj == 0) {
            float4 v0 = make_float4(er[0], er[1], er[2], er[3]);
            float4 v1 = make_float4(er[4], er[5], er[6], er[7]);
            ((float4*)(out + OFF_NODE_EMB + (long)n * 8))[0] = v0;
            ((float4*)(out + OFF_NODE_EMB + (long)n * 8))[1] = v1;
            ((float4*)(g_emb + n * 8))[0] = v0;
            ((float4*)(g_emb + n * 8))[1] = v1;
            float rr = 0.f;
#pragma unroll
            for (int r = 0; r < 8; r++) rr = fmaf(er[r], er[r], rr);
            g_r[n] = rr;
        }
        float rec = __ldg(dnb + jj);
#pragma unroll
        for (int r = 0; r < 8; r++) rec = fmaf(er[r], __ldg(dnw + r * 64 + jj), rec);
        out[OFF_RECON_NODE + (long)n * 64 + jj] = rec;
        __syncthreads();
    }
}

// ---------------------------------------------------------------------------
// K5: adjacency.  adj[i][j] = sigmoid(3*(r_i + r_j - 2<e_i,e_j>) - 1), diag 0.
// ---------------------------------------------------------------------------
__global__ __launch_bounds__(256) void k_adj(float* __restrict__ out) {
    int tid = threadIdx.x;
    int j0 = blockIdx.x * 1024 + tid * 4;
    float ej[4][8], rj[4];
#pragma unroll
    for (int q = 0; q < 4; q++) {
        int jx = j0 + q;
        if (jx < N_NODES) {
            float4 a = ((const float4*)(g_emb + jx * 8))[0];
            float4 b = ((const float4*)(g_emb + jx * 8))[1];
            ej[q][0] = a.x; ej[q][1] = a.y; ej[q][2] = a.z; ej[q][3] = a.w;
            ej[q][4] = b.x; ej[q][5] = b.y; ej[q][6] = b.z; ej[q][7] = b.w;
            rj[q] = g_r[jx];
        } else {
#pragma unroll
            for (int r = 0; r < 8; r++) ej[q][r] = 0.f;
            rj[q] = 0.f;
        }
    }
    int ibase = blockIdx.y * 16;   // 625 * 16 == 10000 exactly
    for (int ii = 0; ii < 16; ii++) {
        int i = ibase + ii;
        float4 a = ((const float4*)(g_emb + i * 8))[0];
        float4 b = ((const float4*)(g_emb + i * 8))[1];
        float eiv[8] = {a.x, a.y, a.z, a.w, b.x, b.y, b.z, b.w};
        float ri = g_r[i];
        float res[4];
#pragma unroll
        for (int q = 0; q < 4; q++) {
            float dot = 0.f;
#pragma unroll
            for (int r = 0; r < 8; r++) dot = fmaf(eiv[r], ej[q][r], dot);
            float d2 = ri + rj[q] - 2.f * dot;
            float ex = __expf(1.f - 3.f * d2);
            float v = __fdividef(1.f, 1.f + ex);
            res[q] = (j0 + q == i) ? 0.f : v;
        }
        if (j0 < N_NODES) {
            *((float4*)(out + OFF_ADJ + (long)i * N_NODES + j0)) =
                make_float4(res[0], res[1], res[2], res[3]);
        }
    }
}

// ---------------------------------------------------------------------------
extern "C" void kernel_launch(void* const* d_in, const int* in_sizes, int n_in,
                              void* d_out, int out_size) {
    const float* nf     = (const float*)d_in[0];
    const int*   ei     = (const int*)  d_in[1];
    const float* ea     = (const float*)d_in[2];
    const float* coords = (const float*)d_in[3];
    const float* ew1    = (const float*)d_in[4];
    const float* eb1    = (const float*)d_in[5];
    const float* ew2    = (const float*)d_in[6];
    const float* eb2    = (const float*)d_in[7];
    const float* cw1    = (const float*)d_in[8];
    const float* cb1    = (const float*)d_in[9];
    const float* cw2    = (const float*)d_in[10];
    const float* nw1    = (const float*)d_in[11];
    const float* nb1    = (const float*)d_in[12];
    const float* nw2    = (const float*)d_in[13];
    const float* nb2    = (const float*)d_in[14];
    const float* fnw    = (const float*)d_in[15];
    const float* fnb    = (const float*)d_in[16];
    const float* few    = (const float*)d_in[17];
    const float* feb    = (const float*)d_in[18];
    const float* dnw    = (const float*)d_in[19];
    const float* dnb    = (const float*)d_in[20];
    const float* dew    = (const float*)d_in[21];
    const float* deb    = (const float*)d_in[22];
    float* out = (float*)d_out;

    k_init<<<(N_NODES * 32 + 255) / 256, 256>>>(coords, out);
    k_nodeproj<<<592, 128>>>(0, nf, ew1, eb1);             // A = nf@W1[0:64] + b1
    k_nodeproj<<<592, 128>>>(1, nf, ew1 + 64 * 128, 0);    // B = nf@W1[64:128]
    k_edge_fused<<<592, 256>>>(ew1, ew2, eb2, cw1, cb1, cw2, few, feb, dew, deb,
                               ei, ea, coords, out);
    k_node_h<<<592, 256>>>(nw1, nb1, nf, out + OFF_COORD);
    k_node_out<<<592, 256>>>(nw2, nb2, fnw, fnb, dnw, dnb, out);
    dim3 gadj((N_NODES + 1023) / 1024, N_NODES / 16);
    k_adj<<<gadj, 256>>>(out);
}

// round 3
// speedup vs baseline: 1.9198x; 1.4295x over previous
#include <cuda_runtime.h>
#include <math.h>

#define N_NODES 10000
#define N_EDGES 320000
#define EPG 8            // edges per group per iteration
#define EPB 16           // edges per block per iteration (2 groups)

// output region offsets in floats
#define OFF_NODE_EMB   0L
#define OFF_EDGE_EMB   80000L
#define OFF_RECON_NODE 2640000L
#define OFF_RECON_EDGE 3280000L
#define OFF_ADJ        13520000L
#define OFF_COORD      113520000L

__device__ float g_A[N_NODES * 128];          // nf @ W1[0:64]  + b1
__device__ float g_B[N_NODES * 128];          // nf @ W1[64:128]
__device__ float g_hn[N_NODES * 128];         // relu(node layer-1)
__device__ float g_agg[N_NODES * 32];         // segment_sum(edge_out)
__device__ float g_emb[N_NODES * 8];          // node_emb copy for adj kernel
__device__ float g_r[N_NODES];                // ||node_emb||^2

// ---------------------------------------------------------------------------
__global__ void k_init(const float* __restrict__ coords, float* __restrict__ out) {
    int i = blockIdx.x * blockDim.x + threadIdx.x;
    if (i < N_NODES * 32) g_agg[i] = 0.f;
    if (i < N_NODES * 3)  out[OFF_COORD + i] = coords[i];
}

// ---------------------------------------------------------------------------
__global__ __launch_bounds__(128) void k_nodeproj(int which,
                                                  const float* __restrict__ nf,
                                                  const float* __restrict__ w,   // [64,128]
                                                  const float* __restrict__ b) {
    __shared__ float ws[64 * 128];
    __shared__ float xs[64];
    float* dst = which ? g_B : g_A;
    int tid = threadIdx.x;
    for (int i = tid; i < 64 * 128; i += 128) ws[i] = w[i];
    float bias = b ? b[tid] : 0.f;
    __syncthreads();
    for (int n = blockIdx.x; n < N_NODES; n += gridDim.x) {
        if (tid < 64) xs[tid] = nf[n * 64 + tid];
        __syncthreads();
        float acc = bias;
#pragma unroll
        for (int f = 0; f < 64; f++) acc = fmaf(xs[f], ws[f * 128 + tid], acc);
        dst[n * 128 + tid] = acc;
        __syncthreads();
    }
}

// ---------------------------------------------------------------------------
// K2: FUSED edge layers, 8 edges per group per iteration.
// 256 threads = 2 groups x 128.  thread k in group: kq = k>>5 (warp), j = lane.
// ---------------------------------------------------------------------------
__global__ __launch_bounds__(256, 2) void k_edge_fused(
        const float* __restrict__ ew1,  // [161,128]
        const float* __restrict__ ew2, const float* __restrict__ eb2,
        const float* __restrict__ cw1, const float* __restrict__ cb1,
        const float* __restrict__ cw2,
        const float* __restrict__ few, const float* __restrict__ feb,
        const float* __restrict__ dew, const float* __restrict__ deb,
        const int* __restrict__ ei, const float* __restrict__ ea,
        const float* __restrict__ coords,
        float* __restrict__ out) {
    __shared__ __align__(16) float eas[2][EPG][32];
    __shared__ __align__(16) float hs[2][EPG][128];
    __shared__ float part[2][EPG][4][32];
    __shared__ float geo[2][EPG][4];       // d0,d1,d2,radial
    __shared__ int   rc[2][EPG][2];
    __shared__ float s_b2[32], s_fcw[256], s_fcb[8], s_cw1[64], s_dew[256], s_deb[32], s_misc[4];
    int tid = threadIdx.x;
    int g = tid >> 7, k = tid & 127, kq = (tid >> 5) & 3, j = tid & 31;

    if (tid < 32) { s_b2[tid] = eb2[tid]; s_deb[tid] = deb[tid]; }
    s_fcw[tid] = few[tid];
    s_dew[tid] = dew[tid];
    if (tid < 64) s_cw1[tid] = cw1[tid];
    if (tid < 8)  s_fcb[tid] = feb[tid];
    if (tid == 0) { s_misc[0] = cb1[0]; s_misc[1] = cb1[1]; s_misc[2] = cw2[0]; s_misc[3] = cw2[1]; }

    float w1e[32];
#pragma unroll
    for (int t = 0; t < 32; t++) w1e[t] = ew1[(128 + t) * 128 + k];
    float w1r = ew1[160 * 128 + k];
    float w2r[32];
#pragma unroll
    for (int t = 0; t < 32; t++) w2r[t] = ew2[(kq * 32 + t) * 32 + j];
    __syncthreads();

    for (int base = blockIdx.x * EPB; base < N_EDGES; base += gridDim.x * EPB) {
        int e0 = base + g * EPG;
        // ---- stage: indices, coord geometry, edge_attr ----
        if (k < EPG) {
            int e = e0 + k;
            int r = ei[e], c = ei[N_EDGES + e];
            rc[g][k][0] = r; rc[g][k][1] = c;
            float d0 = coords[r * 3 + 0] - coords[c * 3 + 0];
            float d1 = coords[r * 3 + 1] - coords[c * 3 + 1];
            float d2 = coords[r * 3 + 2] - coords[c * 3 + 2];
            geo[g][k][0] = d0; geo[g][k][1] = d1; geo[g][k][2] = d2;
            geo[g][k][3] = d0 * d0 + d1 * d1 + d2 * d2;
        }
        {
            int ie = k >> 4, c2 = (k & 15) * 2;
            float2 v = *(const float2*)(ea + (long)(e0 + ie) * 32 + c2);
            eas[g][ie][c2] = v.x; eas[g][ie][c2 + 1] = v.y;
        }
        __syncthreads();

        // ---- gathers (MLP=16) + layer 1 ----
        float h[EPG];
#pragma unroll
        for (int i = 0; i < EPG; i++) {
            int r = rc[g][i][0], c = rc[g][i][1];
            h[i] = g_A[r * 128 + k] + g_B[c * 128 + k] + geo[g][i][3] * w1r;
        }
#pragma unroll
        for (int i = 0; i < EPG; i++) {
            const float4* ev = (const float4*)eas[g][i];
#pragma unroll
            for (int q = 0; q < 8; q++) {
                float4 v = ev[q];
                h[i] = fmaf(v.x, w1e[q * 4 + 0], h[i]);
                h[i] = fmaf(v.y, w1e[q * 4 + 1], h[i]);
                h[i] = fmaf(v.z, w1e[q * 4 + 2], h[i]);
                h[i] = fmaf(v.w, w1e[q * 4 + 3], h[i]);
            }
            hs[g][i][k] = fmaxf(h[i], 0.f);
        }
        __syncthreads();

        // ---- layer 2: warp kq reduces its 32-k slice for all 8 edges ----
#pragma unroll
        for (int i = 0; i < EPG; i++) {
            const float4* hv = (const float4*)(hs[g][i] + kq * 32);
            float p = 0.f;
#pragma unroll
            for (int q = 0; q < 8; q++) {
                float4 v = hv[q];
                p = fmaf(v.x, w2r[q * 4 + 0], p);
                p = fmaf(v.y, w2r[q * 4 + 1], p);
                p = fmaf(v.z, w2r[q * 4 + 2], p);
                p = fmaf(v.w, w2r[q * 4 + 3], p);
            }
            part[g][i][kq][j] = p;
        }
        __syncthreads();

        // ---- epilogue: warp kq handles edges kq*2 and kq*2+1 ----
#pragma unroll
        for (int s = 0; s < 2; s++) {
            int i = kq * 2 + s;
            int e = e0 + i;
            float ov = part[g][i][0][j] + part[g][i][1][j] + part[g][i][2][j]
                     + part[g][i][3][j] + s_b2[j];
            int row = rc[g][i][0];
            atomicAdd(&g_agg[row * 32 + j], ov);
            float p[10];
#pragma unroll
            for (int r = 0; r < 8; r++) p[r] = ov * s_fcw[j * 8 + r];
            p[8] = ov * s_cw1[j * 2 + 0];
            p[9] = ov * s_cw1[j * 2 + 1];
#pragma unroll
            for (int off = 16; off > 0; off >>= 1) {
#pragma unroll
                for (int r = 0; r < 10; r++) p[r] += __shfl_xor_sync(0xffffffffu, p[r], off);
            }
            float er[8];
#pragma unroll
            for (int r = 0; r < 8; r++) er[r] = p[r] + s_fcb[r];
            if (j == 0) {
                float4* o = (float4*)(out + OFF_EDGE_EMB + (long)e * 8);
                o[0] = make_float4(er[0], er[1], er[2], er[3]);
                o[1] = make_float4(er[4], er[5], er[6], er[7]);
            }
            float rec = s_deb[j];
#pragma unroll
            for (int r = 0; r < 8; r++) rec = fmaf(er[r], s_dew[r * 32 + j], rec);
            out[OFF_RECON_EDGE + (long)e * 32 + j] = rec;
            float wz = fmaxf(p[8] + s_misc[0], 0.f) * s_misc[2] +
                       fmaxf(p[9] + s_misc[1], 0.f) * s_misc[3];
            if (j < 3) {
                float radial = geo[g][i][3];
                float inv = 1.0f / (sqrtf(radial) + 1.0f);
                atomicAdd(out + OFF_COORD + row * 3 + j, geo[g][i][j] * inv * wz);
            }
        }
        __syncthreads();   // protect rc/geo/eas from next iteration's stage
    }
}

// ---------------------------------------------------------------------------
__global__ __launch_bounds__(256) void k_node_h(const float* __restrict__ nw1,  // [99,128]
                                                const float* __restrict__ nb1,
                                                const float* __restrict__ nf,
                                                const float* __restrict__ outc) {
    int tid = threadIdx.x;
    int k = tid & 127, slot = tid >> 7, lane = tid & 31;
    float bias = nb1[k];
    float wc0 = nw1[96 * 128 + k], wc1 = nw1[97 * 128 + k], wc2 = nw1[98 * 128 + k];
    for (int n0 = blockIdx.x * 2; n0 < N_NODES; n0 += gridDim.x * 2) {
        int n = n0 + slot;
        float xa = nf[n * 64 + lane];
        float xb = nf[n * 64 + 32 + lane];
        float xc = g_agg[n * 32 + lane];
        float h = bias;
#pragma unroll
        for (int t = 0; t < 32; t++)
            h = fmaf(__shfl_sync(0xffffffffu, xa, t), __ldg(nw1 + t * 128 + k), h);
#pragma unroll
        for (int t = 0; t < 32; t++)
            h = fmaf(__shfl_sync(0xffffffffu, xb, t), __ldg(nw1 + (32 + t) * 128 + k), h);
#pragma unroll
        for (int t = 0; t < 32; t++)
            h = fmaf(__shfl_sync(0xffffffffu, xc, t), __ldg(nw1 + (64 + t) * 128 + k), h);
        h = fmaf(outc[n * 3 + 0], wc0, h);
        h = fmaf(outc[n * 3 + 1], wc1, h);
        h = fmaf(outc[n * 3 + 2], wc2, h);
        g_hn[n * 128 + k] = fmaxf(h, 0.f);
    }
}

// ---------------------------------------------------------------------------
__global__ __launch_bounds__(256) void k_node_out(
        const float* __restrict__ nw2, const float* __restrict__ nb2,
        const float* __restrict__ fnw, const float* __restrict__ fnb,
        const float* __restrict__ dnw, const float* __restrict__ dnb,
        float* __restrict__ out) {
    __shared__ float ps[4][2][8];
    int tid = threadIdx.x;
    int slot = tid >> 6, jj = tid & 63, half = (tid >> 5) & 1, lane = tid & 31;
    float bias = nb2[jj];
    for (int n0 = blockIdx.x * 4; n0 < N_NODES; n0 += gridDim.x * 4) {
        int n = n0 + slot;
        const float* hrow = g_hn + n * 128;
        float acc = bias;
#pragma unroll 8
        for (int kk = 0; kk < 128; kk++)
            acc = fmaf(__ldg(hrow + kk), __ldg(nw2 + kk * 64 + jj), acc);
        float p[8];
#pragma unroll
        for (int r = 0; r < 8; r++) p[r] = acc * __ldg(fnw + jj * 8 + r);
#pragma unroll
        for (int off = 16; off > 0; off >>= 1) {
#pragma unroll
            for (int r = 0; r < 8; r++) p[r] += __shfl_xor_sync(0xffffffffu, p[r], off);
        }
        if (lane == 0) {
#pragma unroll
            for (int r = 0; r < 8; r++) ps[slot][half][r] = p[r];
        }
        __syncthreads();
        float er[8];
#pragma unroll
        for (int r = 0; r < 8; r++) er[r] = ps[slot][0][r] + ps[slot][1][r] + __ldg(fnb + r);
        if (jj == 0) {
            float4 v0 = make_float4(er[0], er[1], er[2], er[3]);
            float4 v1 = make_float4(er[4], er[5], er[6], er[7]);
            ((float4*)(out + OFF_NODE_EMB + (long)n * 8))[0] = v0;
            ((float4*)(out + OFF_NODE_EMB + (long)n * 8))[1] = v1;
            ((float4*)(g_emb + n * 8))[0] = v0;
            ((float4*)(g_emb + n * 8))[1] = v1;
            float rr = 0.f;
#pragma unroll
            for (int r = 0; r < 8; r++) rr = fmaf(er[r], er[r], rr);
            g_r[n] = rr;
        }
        float rec = __ldg(dnb + jj);
#pragma unroll
        for (int r = 0; r < 8; r++) rec = fmaf(er[r], __ldg(dnw + r * 64 + jj), rec);
        out[OFF_RECON_NODE + (long)n * 64 + jj] = rec;
        __syncthreads();
    }
}

// ---------------------------------------------------------------------------
__global__ __launch_bounds__(256) void k_adj(float* __restrict__ out) {
    int tid = threadIdx.x;
    int j0 = blockIdx.x * 1024 + tid * 4;
    float ej[4][8], rj[4];
#pragma unroll
    for (int q = 0; q < 4; q++) {
        int jx = j0 + q;
        if (jx < N_NODES) {
            float4 a = ((const float4*)(g_emb + jx * 8))[0];
            float4 b = ((const float4*)(g_emb + jx * 8))[1];
            ej[q][0] = a.x; ej[q][1] = a.y; ej[q][2] = a.z; ej[q][3] = a.w;
            ej[q][4] = b.x; ej[q][5] = b.y; ej[q][6] = b.z; ej[q][7] = b.w;
            rj[q] = g_r[jx];
        } else {
#pragma unroll
            for (int r = 0; r < 8; r++) ej[q][r] = 0.f;
            rj[q] = 0.f;
        }
    }
    int ibase = blockIdx.y * 16;
    for (int ii = 0; ii < 16; ii++) {
        int i = ibase + ii;
        float4 a = ((const float4*)(g_emb + i * 8))[0];
        float4 b = ((const float4*)(g_emb + i * 8))[1];
        float eiv[8] = {a.x, a.y, a.z, a.w, b.x, b.y, b.z, b.w};
        float ri = g_r[i];
        float res[4];
#pragma unroll
        for (int q = 0; q < 4; q++) {
            float dot = 0.f;
#pragma unroll
            for (int r = 0; r < 8; r++) dot = fmaf(eiv[r], ej[q][r], dot);
            float d2 = ri + rj[q] - 2.f * dot;
            float ex = __expf(1.f - 3.f * d2);
            float v = __fdividef(1.f, 1.f + ex);
            res[q] = (j0 + q == i) ? 0.f : v;
        }
        if (j0 < N_NODES) {
            *((float4*)(out + OFF_ADJ + (long)i * N_NODES + j0)) =
                make_float4(res[0], res[1], res[2], res[3]);
        }
    }
}

// ---------------------------------------------------------------------------
extern "C" void kernel_launch(void* const* d_in, const int* in_sizes, int n_in,
                              void* d_out, int out_size) {
    const float* nf     = (const float*)d_in[0];
    const int*   ei     = (const int*)  d_in[1];
    const float* ea     = (const float*)d_in[2];
    const float* coords = (const float*)d_in[3];
    const float* ew1    = (const float*)d_in[4];
    const float* eb1    = (const float*)d_in[5];
    const float* ew2    = (const float*)d_in[6];
    const float* eb2    = (const float*)d_in[7];
    const float* cw1    = (const float*)d_in[8];
    const float* cb1    = (const float*)d_in[9];
    const float* cw2    = (const float*)d_in[10];
    const float* nw1    = (const float*)d_in[11];
    const float* nb1    = (const float*)d_in[12];
    const float* nw2    = (const float*)d_in[13];
    const float* nb2    = (const float*)d_in[14];
    const float* fnw    = (const float*)d_in[15];
    const float* fnb    = (const float*)d_in[16];
    const float* few    = (const float*)d_in[17];
    const float* feb    = (const float*)d_in[18];
    const float* dnw    = (const float*)d_in[19];
    const float* dnb    = (const float*)d_in[20];
    const float* dew    = (const float*)d_in[21];
    const float* deb    = (const float*)d_in[22];
    float* out = (float*)d_out;

    k_init<<<(N_NODES * 32 + 255) / 256, 256>>>(coords, out);
    k_nodeproj<<<592, 128>>>(0, nf, ew1, eb1);
    k_nodeproj<<<592, 128>>>(1, nf, ew1 + 64 * 128, 0);
    k_edge_fused<<<592, 256>>>(ew1, ew2, eb2, cw1, cb1, cw2, few, feb, dew, deb,
                               ei, ea, coords, out);
    k_node_h<<<592, 256>>>(nw1, nb1, nf, out + OFF_COORD);
    k_node_out<<<592, 256>>>(nw2, nb2, fnw, fnb, dnw, dnb, out);
    dim3 gadj((N_NODES + 1023) / 1024, N_NODES / 16);
    k_adj<<<gadj, 256>>>(out);
}

// round 5
// speedup vs baseline: 2.0215x; 1.0529x over previous
#include <cuda_runtime.h>
#include <math.h>

#define N_NODES 10000
#define N_EDGES 320000
#define EPG 8            // edges per block per iteration

// output region offsets in floats
#define OFF_NODE_EMB   0L
#define OFF_EDGE_EMB   80000L
#define OFF_RECON_NODE 2640000L
#define OFF_RECON_EDGE 3280000L
#define OFF_ADJ        13520000L
#define OFF_COORD      113520000L

__device__ float g_A[N_NODES * 128];          // nf @ W1[0:64]  + b1
__device__ float g_B[N_NODES * 128];          // nf @ W1[64:128]
__device__ float g_hn[N_NODES * 128];         // relu(node layer-1)
__device__ float g_agg[N_NODES * 32];         // segment_sum(edge_out)
__device__ float g_emb[N_NODES * 8];          // node_emb copy for adj kernel
__device__ float g_r[N_NODES];                // ||node_emb||^2

// ---------------------------------------------------------------------------
__global__ void k_init(const float* __restrict__ coords, float* __restrict__ out) {
    int i = blockIdx.x * blockDim.x + threadIdx.x;
    if (i < N_NODES * 32) g_agg[i] = 0.f;
    if (i < N_NODES * 3)  out[OFF_COORD + i] = coords[i];
}

// ---------------------------------------------------------------------------
__global__ __launch_bounds__(128) void k_nodeproj(int which,
                                                  const float* __restrict__ nf,
                                                  const float* __restrict__ w,   // [64,128]
                                                  const float* __restrict__ b) {
    __shared__ float ws[64 * 128];
    __shared__ float xs[64];
    float* dst = which ? g_B : g_A;
    int tid = threadIdx.x;
    for (int i = tid; i < 64 * 128; i += 128) ws[i] = w[i];
    float bias = b ? b[tid] : 0.f;
    __syncthreads();
    for (int n = blockIdx.x; n < N_NODES; n += gridDim.x) {
        if (tid < 64) xs[tid] = nf[n * 64 + tid];
        __syncthreads();
        float acc = bias;
#pragma unroll
        for (int f = 0; f < 64; f++) acc = fmaf(xs[f], ws[f * 128 + tid], acc);
        dst[n * 128 + tid] = acc;
        __syncthreads();
    }
}

// ---------------------------------------------------------------------------
// K2: FUSED edge layers.  128 threads, EPG=8 edges per iteration.
// Register prefetch of next iteration's ei/coords/ea; transposed epilogue
// weight tables (bank-conflict free).
// ---------------------------------------------------------------------------
__global__ __launch_bounds__(128, 4) void k_edge_fused(
        const float* __restrict__ ew1,  // [161,128]
        const float* __restrict__ ew2, const float* __restrict__ eb2,
        const float* __restrict__ cw1, const float* __restrict__ cb1,
        const float* __restrict__ cw2,
        const float* __restrict__ few, const float* __restrict__ feb,
        const float* __restrict__ dew, const float* __restrict__ deb,
        const int* __restrict__ ei, const float* __restrict__ ea,
        const float* __restrict__ coords,
        float* __restrict__ out) {
    __shared__ __align__(16) float eas[EPG][32];
    __shared__ __align__(16) float hs[EPG][128];
    __shared__ float part[EPG][4][32];
    __shared__ float geo[EPG][4];       // d0,d1,d2,radial
    __shared__ int   rc[EPG][2];
    __shared__ float s_b2[32], s_fcwT[256], s_fcb[8], s_cw1T[64],
                     s_dew[256], s_deb[32], s_misc[4];
    int tid = threadIdx.x;
    int k = tid, kq = tid >> 5, j = tid & 31;

    if (tid < 32) { s_b2[tid] = eb2[tid]; s_deb[tid] = deb[tid]; }
#pragma unroll
    for (int x = tid; x < 256; x += 128) {       // transpose few [32,8] -> [8,32]
        s_fcwT[(x & 7) * 32 + (x >> 3)] = few[x];
        s_dew[x] = dew[x];
    }
    if (tid < 64) s_cw1T[(tid & 1) * 32 + (tid >> 1)] = cw1[tid];  // [32,2]->[2,32]
    if (tid < 8)  s_fcb[tid] = feb[tid];
    if (tid == 0) { s_misc[0] = cb1[0]; s_misc[1] = cb1[1]; s_misc[2] = cw2[0]; s_misc[3] = cw2[1]; }

    float w1e[32];
#pragma unroll
    for (int t = 0; t < 32; t++) w1e[t] = ew1[(128 + t) * 128 + k];
    float w1r = ew1[160 * 128 + k];
    float w2r[32];
#pragma unroll
    for (int t = 0; t < 32; t++) w2r[t] = ew2[(kq * 32 + t) * 32 + j];

    const int stride = gridDim.x * EPG;
    int base = blockIdx.x * EPG;
    const int ie = tid >> 4, c2 = (tid & 15) * 2;

    // ---- initial stage ----
    if (base < N_EDGES) {
        if (k < EPG) {
            int e = base + k;
            int ec = e < N_EDGES ? e : 0;
            int r = ei[ec], c = ei[N_EDGES + ec];
            rc[k][0] = r; rc[k][1] = c;
            float d0 = coords[r * 3 + 0] - coords[c * 3 + 0];
            float d1 = coords[r * 3 + 1] - coords[c * 3 + 1];
            float d2 = coords[r * 3 + 2] - coords[c * 3 + 2];
            geo[k][0] = d0; geo[k][1] = d1; geo[k][2] = d2;
            geo[k][3] = d0 * d0 + d1 * d1 + d2 * d2;
        }
        int e = base + ie; if (e >= N_EDGES) e = N_EDGES - 1;
        float2 v = *(const float2*)(ea + (long)e * 32 + c2);
        eas[ie][c2] = v.x; eas[ie][c2 + 1] = v.y;
    }

    for (; base < N_EDGES; base += stride) {
        int nbase = base + stride;
        bool has_next = nbase < N_EDGES;

        // ---- prefetch next stage into registers (hidden behind compute) ----
        float2 pf_ea = make_float2(0.f, 0.f);
        int pf_r = 0, pf_c = 0;
        float pr0 = 0, pr1 = 0, pr2 = 0, pc0 = 0, pc1 = 0, pc2 = 0;
        if (has_next) {
            int e = nbase + ie; if (e >= N_EDGES) e = N_EDGES - 1;
            pf_ea = *(const float2*)(ea + (long)e * 32 + c2);
            if (k < EPG) {
                int e2 = nbase + k;
                int ec = e2 < N_EDGES ? e2 : 0;
                pf_r = ei[ec]; pf_c = ei[N_EDGES + ec];
                pr0 = coords[pf_r * 3 + 0]; pr1 = coords[pf_r * 3 + 1]; pr2 = coords[pf_r * 3 + 2];
                pc0 = coords[pf_c * 3 + 0]; pc1 = coords[pf_c * 3 + 1]; pc2 = coords[pf_c * 3 + 2];
            }
        }
        __syncthreads();   // sync_a: stage visible

        // ---- issue A/B gathers early ----
        float av[EPG], bv[EPG];
#pragma unroll
        for (int i = 0; i < EPG; i++) {
            av[i] = g_A[rc[i][0] * 128 + k];
            bv[i] = g_B[rc[i][1] * 128 + k];
        }
        // ---- layer 1: ea-dot while gathers are in flight ----
        float h[EPG];
#pragma unroll
        for (int i = 0; i < EPG; i++) {
            const float4* ev = (const float4*)eas[i];
            float acc = 0.f;
#pragma unroll
            for (int q = 0; q < 8; q++) {
                float4 v = ev[q];
                acc = fmaf(v.x, w1e[q * 4 + 0], acc);
                acc = fmaf(v.y, w1e[q * 4 + 1], acc);
                acc = fmaf(v.z, w1e[q * 4 + 2], acc);
                acc = fmaf(v.w, w1e[q * 4 + 3], acc);
            }
            h[i] = acc;
        }
#pragma unroll
        for (int i = 0; i < EPG; i++)
            hs[i][k] = fmaxf(h[i] + av[i] + bv[i] + geo[i][3] * w1r, 0.f);
        __syncthreads();   // sync_b: hs ready

        // ---- layer 2 ----
#pragma unroll
        for (int i = 0; i < EPG; i++) {
            const float4* hv = (const float4*)(hs[i] + kq * 32);
            float p = 0.f;
#pragma unroll
            for (int q = 0; q < 8; q++) {
                float4 v = hv[q];
                p = fmaf(v.x, w2r[q * 4 + 0], p);
                p = fmaf(v.y, w2r[q * 4 + 1], p);
                p = fmaf(v.z, w2r[q * 4 + 2], p);
                p = fmaf(v.w, w2r[q * 4 + 3], p);
            }
            part[i][kq][j] = p;
        }
        __syncthreads();   // sync_c: part ready

        // ---- epilogue: warp kq handles edges kq*2, kq*2+1 ----
#pragma unroll
        for (int s = 0; s < 2; s++) {
            int i = kq * 2 + s;
            int e = base + i;
            bool valid = e < N_EDGES;
            float ov = part[i][0][j] + part[i][1][j] + part[i][2][j]
                     + part[i][3][j] + s_b2[j];
            int row = rc[i][0];
            if (valid) atomicAdd(&g_agg[row * 32 + j], ov);
            float p[10];
#pragma unroll
            for (int r = 0; r < 8; r++) p[r] = ov * s_fcwT[r * 32 + j];
            p[8] = ov * s_cw1T[j];
            p[9] = ov * s_cw1T[32 + j];
#pragma unroll
            for (int off = 16; off > 0; off >>= 1) {
#pragma unroll
                for (int r = 0; r < 10; r++) p[r] += __shfl_xor_sync(0xffffffffu, p[r], off);
            }
            float er[8];
#pragma unroll
            for (int r = 0; r < 8; r++) er[r] = p[r] + s_fcb[r];
            if (valid) {
                if (j == 0) {
                    float4* o = (float4*)(out + OFF_EDGE_EMB + (long)e * 8);
                    o[0] = make_float4(er[0], er[1], er[2], er[3]);
                    o[1] = make_float4(er[4], er[5], er[6], er[7]);
                }
                float rec = s_deb[j];
#pragma unroll
                for (int r = 0; r < 8; r++) rec = fmaf(er[r], s_dew[r * 32 + j], rec);
                out[OFF_RECON_EDGE + (long)e * 32 + j] = rec;
                float wz = fmaxf(p[8] + s_misc[0], 0.f) * s_misc[2] +
                           fmaxf(p[9] + s_misc[1], 0.f) * s_misc[3];
                if (j < 3) {
                    float inv = 1.0f / (sqrtf(geo[i][3]) + 1.0f);
                    atomicAdd(out + OFF_COORD + row * 3 + j, geo[i][j] * inv * wz);
                }
            }
        }
        __syncthreads();   // sync_d: epilogue done, stage may overwrite

        // ---- write next stage from prefetch registers ----
        if (has_next) {
            if (k < EPG) {
                rc[k][0] = pf_r; rc[k][1] = pf_c;
                float d0 = pr0 - pc0, d1 = pr1 - pc1, d2 = pr2 - pc2;
                geo[k][0] = d0; geo[k][1] = d1; geo[k][2] = d2;
                geo[k][3] = d0 * d0 + d1 * d1 + d2 * d2;
            }
            eas[ie][c2] = pf_ea.x; eas[ie][c2 + 1] = pf_ea.y;
        }
    }
}

// ---------------------------------------------------------------------------
__global__ __launch_bounds__(256) void k_node_h(const float* __restrict__ nw1,  // [99,128]
                                                const float* __restrict__ nb1,
                                                const float* __restrict__ nf,
                                                const float* __restrict__ outc) {
    int tid = threadIdx.x;
    int k = tid & 127, slot = tid >> 7, lane = tid & 31;
    float bias = nb1[k];
    float wc0 = nw1[96 * 128 + k], wc1 = nw1[97 * 128 + k], wc2 = nw1[98 * 128 + k];
    for (int n0 = blockIdx.x * 2; n0 < N_NODES; n0 += gridDim.x * 2) {
        int n = n0 + slot;
        float xa = nf[n * 64 + lane];
        float xb = nf[n * 64 + 32 + lane];
        float xc = g_agg[n * 32 + lane];
        float h = bias;
#pragma unroll
        for (int t = 0; t < 32; t++)
            h = fmaf(__shfl_sync(0xffffffffu, xa, t), __ldg(nw1 + t * 128 + k), h);
#pragma unroll
        for (int t = 0; t < 32; t++)
            h = fmaf(__shfl_sync(0xffffffffu, xb, t), __ldg(nw1 + (32 + t) * 128 + k), h);
#pragma unroll
        for (int t = 0; t < 32; t++)
            h = fmaf(__shfl_sync(0xffffffffu, xc, t), __ldg(nw1 + (64 + t) * 128 + k), h);
        h = fmaf(outc[n * 3 + 0], wc0, h);
        h = fmaf(outc[n * 3 + 1], wc1, h);
        h = fmaf(outc[n * 3 + 2], wc2, h);
        g_hn[n * 128 + k] = fmaxf(h, 0.f);
    }
}

// ---------------------------------------------------------------------------
__global__ __launch_bounds__(256) void k_node_out(
        const float* __restrict__ nw2, const float* __restrict__ nb2,
        const float* __restrict__ fnw, const float* __restrict__ fnb,
        const float* __restrict__ dnw, const float* __restrict__ dnb,
        float* __restrict__ out) {
    __shared__ float ps[4][2][8];
    int tid = threadIdx.x;
    int slot = tid >> 6, jj = tid & 63, half = (tid >> 5) & 1, lane = tid & 31;
    float bias = nb2[jj];
    for (int n0 = blockIdx.x * 4; n0 < N_NODES; n0 += gridDim.x * 4) {
        int n = n0 + slot;
        const float* hrow = g_hn + n * 128;
        float acc = bias;
#pragma unroll 8
        for (int kk = 0; kk < 128; kk++)
            acc = fmaf(__ldg(hrow + kk), __ldg(nw2 + kk * 64 + jj), acc);
        float p[8];
#pragma unroll
        for (int r = 0; r < 8; r++) p[r] = acc * __ldg(fnw + jj * 8 + r);
#pragma unroll
        for (int off = 16; off > 0; off >>= 1) {
#pragma unroll
            for (int r = 0; r < 8; r++) p[r] += __shfl_xor_sync(0xffffffffu, p[r], off);
        }
        if (lane == 0) {
#pragma unroll
            for (int r = 0; r < 8; r++) ps[slot][half][r] = p[r];
        }
        __syncthreads();
        float er[8];
#pragma unroll
        for (int r = 0; r < 8; r++) er[r] = ps[slot][0][r] + ps[slot][1][r] + __ldg(fnb + r);
        if (jj == 0) {
            float4 v0 = make_float4(er[0], er[1], er[2], er[3]);
            float4 v1 = make_float4(er[4], er[5], er[6], er[7]);
            ((float4*)(out + OFF_NODE_EMB + (long)n * 8))[0] = v0;
            ((float4*)(out + OFF_NODE_EMB + (long)n * 8))[1] = v1;
            ((float4*)(g_emb + n * 8))[0] = v0;
            ((float4*)(g_emb + n * 8))[1] = v1;
            float rr = 0.f;
#pragma unroll
            for (int r = 0; r < 8; r++) rr = fmaf(er[r], er[r], rr);
            g_r[n] = rr;
        }
        float rec = __ldg(dnb + jj);
#pragma unroll
        for (int r = 0; r < 8; r++) rec = fmaf(er[r], __ldg(dnw + r * 64 + jj), rec);
        out[OFF_RECON_NODE + (long)n * 64 + jj] = rec;
        __syncthreads();
    }
}

// ---------------------------------------------------------------------------
__global__ __launch_bounds__(256) void k_adj(float* __restrict__ out) {
    int tid = threadIdx.x;
    int j0 = blockIdx.x * 1024 + tid * 4;
    float ej[4][8], rj[4];
#pragma unroll
    for (int q = 0; q < 4; q++) {
        int jx = j0 + q;
        if (jx < N_NODES) {
            float4 a = ((const float4*)(g_emb + jx * 8))[0];
            float4 b = ((const float4*)(g_emb + jx * 8))[1];
            ej[q][0] = a.x; ej[q][1] = a.y; ej[q][2] = a.z; ej[q][3] = a.w;
            ej[q][4] = b.x; ej[q][5] = b.y; ej[q][6] = b.z; ej[q][7] = b.w;
            rj[q] = g_r[jx];
        } else {
#pragma unroll
            for (int r = 0; r < 8; r++) ej[q][r] = 0.f;
            rj[q] = 0.f;
        }
    }
    int ibase = blockIdx.y * 16;
    for (int ii = 0; ii < 16; ii++) {
        int i = ibase + ii;
        float4 a = ((const float4*)(g_emb + i * 8))[0];
        float4 b = ((const float4*)(g_emb + i * 8))[1];
        float eiv[8] = {a.x, a.y, a.z, a.w, b.x, b.y, b.z, b.w};
        float ri = g_r[i];
        float res[4];
#pragma unroll
        for (int q = 0; q < 4; q++) {
            float dot = 0.f;
#pragma unroll
            for (int r = 0; r < 8; r++) dot = fmaf(eiv[r], ej[q][r], dot);
            float d2 = ri + rj[q] - 2.f * dot;
            float ex = __expf(1.f - 3.f * d2);
            float v = __fdividef(1.f, 1.f + ex);
            res[q] = (j0 + q == i) ? 0.f : v;
        }
        if (j0 < N_NODES) {
            __stcs((float4*)(out + OFF_ADJ + (long)i * N_NODES + j0),
                   make_float4(res[0], res[1], res[2], res[3]));
        }
    }
}

// ---------------------------------------------------------------------------
extern "C" void kernel_launch(void* const* d_in, const int* in_sizes, int n_in,
                              void* d_out, int out_size) {
    const float* nf     = (const float*)d_in[0];
    const int*   ei     = (const int*)  d_in[1];
    const float* ea     = (const float*)d_in[2];
    const float* coords = (const float*)d_in[3];
    const float* ew1    = (const float*)d_in[4];
    const float* eb1    = (const float*)d_in[5];
    const float* ew2    = (const float*)d_in[6];
    const float* eb2    = (const float*)d_in[7];
    const float* cw1    = (const float*)d_in[8];
    const float* cb1    = (const float*)d_in[9];
    const float* cw2    = (const float*)d_in[10];
    const float* nw1    = (const float*)d_in[11];
    const float* nb1    = (const float*)d_in[12];
    const float* nw2    = (const float*)d_in[13];
    const float* nb2    = (const float*)d_in[14];
    const float* fnw    = (const float*)d_in[15];
    const float* fnb    = (const float*)d_in[16];
    const float* few    = (const float*)d_in[17];
    const float* feb    = (const float*)d_in[18];
    const float* dnw    = (const float*)d_in[19];
    const float* dnb    = (const float*)d_in[20];
    const float* dew    = (const float*)d_in[21];
    const float* deb    = (const float*)d_in[22];
    float* out = (float*)d_out;

    k_init<<<(N_NODES * 32 + 255) / 256, 256>>>(coords, out);
    k_nodeproj<<<592, 128>>>(0, nf, ew1, eb1);
    k_nodeproj<<<592, 128>>>(1, nf, ew1 + 64 * 128, 0);
    k_edge_fused<<<592, 128>>>(ew1, ew2, eb2, cw1, cb1, cw2, few, feb, dew, deb,
                               ei, ea, coords, out);
    k_node_h<<<592, 256>>>(nw1, nb1, nf, out + OFF_COORD);
    k_node_out<<<592, 256>>>(nw2, nb2, fnw, fnb, dnw, dnb, out);
    dim3 gadj((N_NODES + 1023) / 1024, N_NODES / 16);
    k_adj<<<gadj, 256>>>(out);
}